// round 5
// baseline (speedup 1.0000x reference)
#include <cuda_runtime.h>
#include <math.h>
#include <float.h>

// Problem constants
#define NB 4
#define NL 1024
#define NC 1024
#define NH 16
#define NDK 64

// packed fp32x2 helpers (Blackwell packed-FP32 pipe; ptxas never auto-fuses)
#define PACK2(d, x)      asm("mov.b64 %0, {%1, %2};" : "=l"(d) : "f"(x), "f"(x))
#define FMA2(d, a, b)    asm("fma.rn.f32x2 %0, %1, %2, %0;" : "+l"(d) : "l"(a), "l"(b))
#define UNPACK2(lo, hi, v) do { unsigned _ulo, _uhi; \
    asm("mov.b64 {%0, %1}, %2;" : "=r"(_ulo), "=r"(_uhi) : "l"(v)); \
    lo = __uint_as_float(_ulo); hi = __uint_as_float(_uhi); } while (0)

// -------- scratch (device globals: allocation-free) --------
__device__ float g_gates[4 * 5 * 1024];                      // [i][e][o]
__device__ float g_W[(size_t)4 * 5 * 1024 * 1024];           // [i][t][o][c]  84 MB
__device__ float g_qkv[3][(size_t)NB * NL * NC];             // projected Q,K,V   50 MB
__device__ float g_att[(size_t)NB * NL * NC];                // attention concat  17 MB
__device__ float g_scores[(size_t)NB * NH * NL * NL];        // scores/attn       268 MB

// ============================================================
// 1) gates: softmax over experts of (gate_w + gate_b), per (i,o)
// ============================================================
__global__ void gate_kernel(const float* __restrict__ gw, const float* __restrict__ gb) {
    int idx = blockIdx.x * blockDim.x + threadIdx.x;
    if (idx >= 4 * 1024) return;
    int i = idx >> 10, o = idx & 1023;
    float v[5], m = -FLT_MAX;
#pragma unroll
    for (int e = 0; e < 5; e++) {
        int off = i * 5120 + e * 1024 + o;
        v[e] = gw[off] + gb[off];
        m = fmaxf(m, v[e]);
    }
    float s = 0.f;
#pragma unroll
    for (int e = 0; e < 5; e++) { v[e] = expf(v[e] - m); s += v[e]; }
    float inv = 1.f / s;
#pragma unroll
    for (int e = 0; e < 5; e++) g_gates[(i * 5 + e) * 1024 + o] = v[e] * inv;
}

// ============================================================
// 2) combined conv weights: W[i][t][o][c] = sum_e g[e,o]*expert_e[o,c,t]
// ============================================================
__global__ void build_w_kernel(const float* __restrict__ c5, const float* __restrict__ c3,
                               const float* __restrict__ c1, const float* __restrict__ a3,
                               const float* __restrict__ a5) {
    int idx = blockIdx.x * blockDim.x + threadIdx.x;   // 4M threads: (i,o,c)
    if (idx >= 4 * 1024 * 1024) return;
    int i = idx >> 20;
    int o = (idx >> 10) & 1023;
    int c = idx & 1023;
    int gbase = i * 5120 + o;
    float g0 = g_gates[gbase];
    float g1 = g_gates[gbase + 1024];
    float g2 = g_gates[gbase + 2048];
    float g3 = g_gates[gbase + 3072];
    float g4 = g_gates[gbase + 4096];
    size_t oc = ((size_t)i << 20) + ((size_t)o << 10) + c;
    const float* p5 = c5 + oc * 5;
    const float* p3 = c3 + oc * 3;
    float base = g4 * a5[oc] * 0.2f;                 // avg5 expert: every tap
    float mid  = g3 * a3[oc] * (1.f / 3.f);          // avg3 expert: taps 1..3
    float w0 = g0 * p5[0] + base;
    float w1 = g0 * p5[1] + g1 * p3[0] + mid + base;
    float w2 = g0 * p5[2] + g1 * p3[1] + g2 * c1[oc] + mid + base;
    float w3 = g0 * p5[3] + g1 * p3[2] + mid + base;
    float w4 = g0 * p5[4] + base;
    size_t wb = (((size_t)(i * 5) << 10) + o) * 1024 + c;
    const size_t TS = (size_t)1024 * 1024;
    g_W[wb]          = w0;
    g_W[wb + TS]     = w1;
    g_W[wb + 2 * TS] = w2;
    g_W[wb + 3 * TS] = w3;
    g_W[wb + 4 * TS] = w4;
}

// ============================================================
// 3) conv-as-GEMM body: y[b,l,o] = sum_t sum_c W[wi][t][o][c]*x[b,l+t-2,c]
//    128x128 tile, 256 thr, 8x8 microtile (packed f32x2),
//    double-buffered smem, flattened (tap, k-chunk) pipeline of 320 steps.
// ============================================================
__device__ __forceinline__
void conv_body(const float* __restrict__ x, int wi, float* __restrict__ y, int relu,
               float As[2][16][132], float Bs[2][16][132]) {
    int b  = blockIdx.y >> 3;
    int l0 = (blockIdx.y & 7) << 7;
    int o0 = blockIdx.x << 7;
    int tid = threadIdx.x;
    int tx = tid & 15, ty = tid >> 4;

    unsigned long long acc2[8][4];   // 8 rows x 4 packed pairs (8 cols)
#pragma unroll
    for (int i = 0; i < 8; i++)
#pragma unroll
        for (int j = 0; j < 4; j++) acc2[i][j] = 0ULL;  // {0.f,0.f}

    int ar = tid >> 2;            // 0..63
    int ak = (tid & 3) << 2;      // 0,4,8,12
    const float* xb = x + (((size_t)b) << 20);
    const float* wbase = g_W + (((size_t)(wi * 5)) << 20);

    const int NSTEP = 5 * 64;     // taps x k-chunks
    float4 pa[2], pb[2];

#define CONV_LOAD(s) do { \
    int t_ = (s) >> 6; int k0_ = ((s) & 63) << 4; int dl_ = t_ - 2; \
    const float* wb_ = wbase + ((size_t)t_ << 20); \
    _Pragma("unroll") \
    for (int rr = 0; rr < 2; rr++) { \
        int row = ar + (rr << 6); \
        int lp = l0 + row + dl_; \
        pa[rr] = make_float4(0.f, 0.f, 0.f, 0.f); \
        if ((unsigned)lp < 1024u) \
            pa[rr] = *(const float4*)(xb + (size_t)lp * 1024 + k0_ + ak); \
        pb[rr] = *(const float4*)(wb_ + (size_t)(o0 + row) * 1024 + k0_ + ak); \
    } } while (0)

#define CONV_STORE(bf) do { \
    _Pragma("unroll") \
    for (int rr = 0; rr < 2; rr++) { \
        int row = ar + (rr << 6); \
        As[bf][ak + 0][row] = pa[rr].x; As[bf][ak + 1][row] = pa[rr].y; \
        As[bf][ak + 2][row] = pa[rr].z; As[bf][ak + 3][row] = pa[rr].w; \
        Bs[bf][ak + 0][row] = pb[rr].x; Bs[bf][ak + 1][row] = pb[rr].y; \
        Bs[bf][ak + 2][row] = pb[rr].z; Bs[bf][ak + 3][row] = pb[rr].w; \
    } } while (0)

    CONV_LOAD(0);
    CONV_STORE(0);
    __syncthreads();

    for (int s = 0; s < NSTEP; s++) {
        int buf = s & 1;
        if (s + 1 < NSTEP) CONV_LOAD(s + 1);   // prefetch overlaps compute
#pragma unroll
        for (int kk = 0; kk < 16; kk++) {
            float4 a0 = *(const float4*)&As[buf][kk][ty << 3];
            float4 a1 = *(const float4*)&As[buf][kk][(ty << 3) + 4];
            const unsigned long long* bp =
                (const unsigned long long*)&Bs[buf][kk][tx << 3];
            unsigned long long bb0 = bp[0], bb1 = bp[1];
            unsigned long long bb2 = bp[2], bb3 = bp[3];
            float a[8] = {a0.x, a0.y, a0.z, a0.w, a1.x, a1.y, a1.z, a1.w};
#pragma unroll
            for (int i = 0; i < 8; i++) {
                unsigned long long pav;
                PACK2(pav, a[i]);
                FMA2(acc2[i][0], pav, bb0);
                FMA2(acc2[i][1], pav, bb1);
                FMA2(acc2[i][2], pav, bb2);
                FMA2(acc2[i][3], pav, bb3);
            }
        }
        if (s + 1 < NSTEP) CONV_STORE(buf ^ 1);
        __syncthreads();
    }
#undef CONV_LOAD
#undef CONV_STORE

#pragma unroll
    for (int i = 0; i < 8; i++) {
        int l = l0 + (ty << 3) + i;
        float* yr = y + ((((size_t)b) << 10) + l) * 1024 + o0 + (tx << 3);
#pragma unroll
        for (int j = 0; j < 2; j++) {
            float4 v;
            UNPACK2(v.x, v.y, acc2[i][2 * j]);
            UNPACK2(v.z, v.w, acc2[i][2 * j + 1]);
            if (relu) {
                v.x = fmaxf(v.x, 0.f); v.y = fmaxf(v.y, 0.f);
                v.z = fmaxf(v.z, 0.f); v.w = fmaxf(v.w, 0.f);
            }
            *(float4*)(yr + 4 * j) = v;
        }
    }
}

// Q/K/V projections fused into one launch via blockIdx.z
__global__ __launch_bounds__(256)
void conv_qkv_kernel(const float* __restrict__ q, const float* __restrict__ k,
                     const float* __restrict__ v) {
    __shared__ float As[2][16][132];
    __shared__ float Bs[2][16][132];
    int z = blockIdx.z;
    const float* x = (z == 0) ? q : (z == 1) ? k : v;
    conv_body(x, z, g_qkv[z], 1, As, Bs);
}

// final wo projection (reads g_att, no relu)
__global__ __launch_bounds__(256)
void conv_out_kernel(float* __restrict__ out) {
    __shared__ float As[2][16][132];
    __shared__ float Bs[2][16][132];
    conv_body(g_att, 3, out, 0, As, Bs);
}

// ============================================================
// 4) scores = Q K^T / 8 per (b,h): 128x128 tile, K=64
// ============================================================
__global__ __launch_bounds__(256)
void scores_kernel() {
    int kc0 = blockIdx.x << 7;
    int q0  = blockIdx.y << 7;
    int bh  = blockIdx.z;
    int b = bh >> 4, h = bh & 15;
    int tid = threadIdx.x;
    int tx = tid & 15, ty = tid >> 4;
    __shared__ float As[16][132];
    __shared__ float Bs[16][132];
    unsigned long long acc2[8][4];
#pragma unroll
    for (int i = 0; i < 8; i++)
#pragma unroll
        for (int j = 0; j < 4; j++) acc2[i][j] = 0ULL;
    int ar = tid >> 2, ak = (tid & 3) << 2;
    const float* Q = g_qkv[0] + (((size_t)b) << 20) + h * 64;
    const float* K = g_qkv[1] + (((size_t)b) << 20) + h * 64;
    for (int k0 = 0; k0 < 64; k0 += 16) {
#pragma unroll
        for (int rr = 0; rr < 2; rr++) {
            int row = ar + (rr << 6);
            float4 av = *(const float4*)(Q + (q0 + row) * 1024 + k0 + ak);
            As[ak + 0][row] = av.x; As[ak + 1][row] = av.y;
            As[ak + 2][row] = av.z; As[ak + 3][row] = av.w;
            float4 bv = *(const float4*)(K + (kc0 + row) * 1024 + k0 + ak);
            Bs[ak + 0][row] = bv.x; Bs[ak + 1][row] = bv.y;
            Bs[ak + 2][row] = bv.z; Bs[ak + 3][row] = bv.w;
        }
        __syncthreads();
#pragma unroll
        for (int kk = 0; kk < 16; kk++) {
            float4 a0 = *(const float4*)&As[kk][ty << 3];
            float4 a1 = *(const float4*)&As[kk][(ty << 3) + 4];
            const unsigned long long* bp =
                (const unsigned long long*)&Bs[kk][tx << 3];
            unsigned long long bb0 = bp[0], bb1 = bp[1];
            unsigned long long bb2 = bp[2], bb3 = bp[3];
            float a[8] = {a0.x, a0.y, a0.z, a0.w, a1.x, a1.y, a1.z, a1.w};
#pragma unroll
            for (int i = 0; i < 8; i++) {
                unsigned long long pav;
                PACK2(pav, a[i]);
                FMA2(acc2[i][0], pav, bb0);
                FMA2(acc2[i][1], pav, bb1);
                FMA2(acc2[i][2], pav, bb2);
                FMA2(acc2[i][3], pav, bb3);
            }
        }
        __syncthreads();
    }
    float* S = g_scores + (((size_t)bh) << 20);
#pragma unroll
    for (int i = 0; i < 8; i++) {
        float* sr = S + (size_t)(q0 + (ty << 3) + i) * 1024 + kc0 + (tx << 3);
#pragma unroll
        for (int j = 0; j < 2; j++) {
            float4 v;
            UNPACK2(v.x, v.y, acc2[i][2 * j]);
            UNPACK2(v.z, v.w, acc2[i][2 * j + 1]);
            v.x *= 0.125f; v.y *= 0.125f; v.z *= 0.125f; v.w *= 0.125f;
            *(float4*)(sr + 4 * j) = v;
        }
    }
}

// ============================================================
// 5) masked softmax over each score row (length 1024)
//    256 threads/row, one contiguous float4/int4 chunk per thread.
// ============================================================
__global__ void softmax_kernel(const int* __restrict__ mask) {
    int row = blockIdx.x;                 // bh*1024 + q
    int q = row & 1023;
    int b = row >> 14;                    // row / (16*1024)
    float* s = g_scores + ((size_t)row << 10);
    const int* mrow = mask + ((((size_t)b) << 10) + q) * 1024;
    int tid = threadIdx.x;                // 256 threads, 4 contiguous elems each
    float4 sv = *(const float4*)(s + (tid << 2));
    int4  mv = *(const int4*)(mrow + (tid << 2));
    float v[4];
    v[0] = (mv.x != 0) ? sv.x : -FLT_MAX;
    v[1] = (mv.y != 0) ? sv.y : -FLT_MAX;
    v[2] = (mv.z != 0) ? sv.z : -FLT_MAX;
    v[3] = (mv.w != 0) ? sv.w : -FLT_MAX;
    float mx = fmaxf(fmaxf(v[0], v[1]), fmaxf(v[2], v[3]));
    __shared__ float sred[8];
#pragma unroll
    for (int off = 16; off > 0; off >>= 1)
        mx = fmaxf(mx, __shfl_xor_sync(0xffffffffu, mx, off));
    if ((tid & 31) == 0) sred[tid >> 5] = mx;
    __syncthreads();
    if (tid == 0) {
        float m2 = sred[0];
#pragma unroll
        for (int w = 1; w < 8; w++) m2 = fmaxf(m2, sred[w]);
        sred[0] = m2;
    }
    __syncthreads();
    float rowmax = sred[0];
    __syncthreads();
    float sum = 0.f;
#pragma unroll
    for (int j = 0; j < 4; j++) {
        v[j] = expf(v[j] - rowmax);
        sum += v[j];
    }
#pragma unroll
    for (int off = 16; off > 0; off >>= 1)
        sum += __shfl_xor_sync(0xffffffffu, sum, off);
    if ((tid & 31) == 0) sred[tid >> 5] = sum;
    __syncthreads();
    if (tid == 0) {
        float s2 = 0.f;
#pragma unroll
        for (int w = 0; w < 8; w++) s2 += sred[w];
        sred[0] = s2;
    }
    __syncthreads();
    float inv = 1.f / sred[0];
    float4 ov;
    ov.x = v[0] * inv; ov.y = v[1] * inv;
    ov.z = v[2] * inv; ov.w = v[3] * inv;
    *(float4*)(s + (tid << 2)) = ov;
}

// ============================================================
// 6) out = attn @ V per (b,h): M=1024, N=64, K=1024; 128x64 tile
// ============================================================
__global__ __launch_bounds__(256)
void attnv_kernel() {
    int m0 = blockIdx.x << 7;
    int bh = blockIdx.y;
    int b = bh >> 4, h = bh & 15;
    int tid = threadIdx.x;
    int tx = tid & 15, ty = tid >> 4;
    __shared__ float As[16][132];
    __shared__ float Bs[16][68];
    unsigned long long acc2[8][2];
#pragma unroll
    for (int i = 0; i < 8; i++)
#pragma unroll
        for (int j = 0; j < 2; j++) acc2[i][j] = 0ULL;
    const float* A = g_scores + (((size_t)bh) << 20);
    const float* V = g_qkv[2] + (((size_t)b) << 20) + h * 64;
    int ar = tid >> 2, ak = (tid & 3) << 2;
    int bkk = tid >> 4, bc = (tid & 15) << 2;
    for (int k0 = 0; k0 < 1024; k0 += 16) {
#pragma unroll
        for (int rr = 0; rr < 2; rr++) {
            int row = ar + (rr << 6);
            float4 av = *(const float4*)(A + (size_t)(m0 + row) * 1024 + k0 + ak);
            As[ak + 0][row] = av.x; As[ak + 1][row] = av.y;
            As[ak + 2][row] = av.z; As[ak + 3][row] = av.w;
        }
        {
            float4 bv = *(const float4*)(V + (k0 + bkk) * 1024 + bc);
            *(float4*)&Bs[bkk][bc] = bv;
        }
        __syncthreads();
#pragma unroll
        for (int kk = 0; kk < 16; kk++) {
            float4 a0 = *(const float4*)&As[kk][ty << 3];
            float4 a1 = *(const float4*)&As[kk][(ty << 3) + 4];
            const unsigned long long* bp =
                (const unsigned long long*)&Bs[kk][tx << 2];
            unsigned long long bb0 = bp[0], bb1 = bp[1];
            float a[8] = {a0.x, a0.y, a0.z, a0.w, a1.x, a1.y, a1.z, a1.w};
#pragma unroll
            for (int i = 0; i < 8; i++) {
                unsigned long long pav;
                PACK2(pav, a[i]);
                FMA2(acc2[i][0], pav, bb0);
                FMA2(acc2[i][1], pav, bb1);
            }
        }
        __syncthreads();
    }
#pragma unroll
    for (int i = 0; i < 8; i++) {
        float4 v;
        UNPACK2(v.x, v.y, acc2[i][0]);
        UNPACK2(v.z, v.w, acc2[i][1]);
        float* yr = g_att + ((((size_t)b) << 10) + m0 + (ty << 3) + i) * 1024 + h * 64 + (tx << 2);
        *(float4*)yr = v;
    }
}

// ============================================================
// launch
// ============================================================
extern "C" void kernel_launch(void* const* d_in, const int* in_sizes, int n_in,
                              void* d_out, int out_size) {
    const float* q   = (const float*)d_in[0];
    const float* k   = (const float*)d_in[1];
    const float* v   = (const float*)d_in[2];
    const float* gw  = (const float*)d_in[3];
    const float* gb  = (const float*)d_in[4];
    const float* c5  = (const float*)d_in[5];
    const float* c3  = (const float*)d_in[6];
    const float* c1  = (const float*)d_in[7];
    const float* a3  = (const float*)d_in[8];
    const float* a5  = (const float*)d_in[9];
    const int*   msk = (const int*)d_in[10];
    float* out = (float*)d_out;

    gate_kernel<<<16, 256>>>(gw, gb);
    build_w_kernel<<<16384, 256>>>(c5, c3, c1, a3, a5);

    conv_qkv_kernel<<<dim3(8, 32, 3), 256>>>(q, k, v);

    scores_kernel<<<dim3(8, 8, 64), 256>>>();
    softmax_kernel<<<65536, 256>>>(msk);
    attnv_kernel<<<dim3(8, 64), 256>>>();

    conv_out_kernel<<<dim3(8, 32, 1), 256>>>(out);
}

// round 16
// speedup vs baseline: 1.8112x; 1.8112x over previous
#include <cuda_runtime.h>
#include <math.h>
#include <float.h>
#include <stdint.h>

// Problem constants
#define NB 4
#define NL 1024
#define NC 1024
#define NH 16
#define NDK 64

// packed fp32x2 helpers (attention path; measured 38 TF/s on scores)
#define PACK2(d, x)      asm("mov.b64 %0, {%1, %2};" : "=l"(d) : "f"(x), "f"(x))
#define FMA2(d, a, b)    asm("fma.rn.f32x2 %0, %1, %2, %0;" : "+l"(d) : "l"(a), "l"(b))
#define UNPACK2(lo, hi, v) do { unsigned _ulo, _uhi; \
    asm("mov.b64 {%0, %1}, %2;" : "=r"(_ulo), "=r"(_uhi) : "l"(v)); \
    lo = __uint_as_float(_ulo); hi = __uint_as_float(_uhi); } while (0)

// tf32 mma.sync (base PTX sm_80+, compiles for compute_103; runs on tensor cores)
#define MMA_TF32(d, a, b) \
    asm volatile("mma.sync.aligned.m16n8k8.row.col.f32.tf32.tf32.f32 " \
        "{%0,%1,%2,%3}, {%4,%5,%6,%7}, {%8,%9}, {%0,%1,%2,%3};" \
        : "+f"((d)[0]), "+f"((d)[1]), "+f"((d)[2]), "+f"((d)[3]) \
        : "r"((a)[0]), "r"((a)[1]), "r"((a)[2]), "r"((a)[3]), \
          "r"((b)[0]), "r"((b)[1]))

// round-to-nearest fp32 -> tf32 (avoids the systematic truncation bias of
// feeding raw fp32 bits to the .tf32 MMA)
__device__ __forceinline__ float to_tf32(float x) {
    uint32_t r;
    asm("cvt.rna.tf32.f32 %0, %1;" : "=r"(r) : "f"(x));
    return __uint_as_float(r);
}

// -------- scratch (device globals: allocation-free) --------
__device__ float g_gates[4 * 5 * 1024];                      // [i][e][o]
__device__ float g_W[(size_t)4 * 5 * 1024 * 1024];           // [i][t][o][c]  84 MB
__device__ float g_qkv[3][(size_t)NB * NL * NC];             // projected Q,K,V   50 MB
__device__ float g_att[(size_t)NB * NL * NC];                // attention concat  17 MB
__device__ float g_scores[(size_t)NB * NH * NL * NL];        // scores/attn       268 MB

// ============================================================
// 1) gates: softmax over experts of (gate_w + gate_b), per (i,o)
// ============================================================
__global__ void gate_kernel(const float* __restrict__ gw, const float* __restrict__ gb) {
    int idx = blockIdx.x * blockDim.x + threadIdx.x;
    if (idx >= 4 * 1024) return;
    int i = idx >> 10, o = idx & 1023;
    float v[5], m = -FLT_MAX;
#pragma unroll
    for (int e = 0; e < 5; e++) {
        int off = i * 5120 + e * 1024 + o;
        v[e] = gw[off] + gb[off];
        m = fmaxf(m, v[e]);
    }
    float s = 0.f;
#pragma unroll
    for (int e = 0; e < 5; e++) { v[e] = expf(v[e] - m); s += v[e]; }
    float inv = 1.f / s;
#pragma unroll
    for (int e = 0; e < 5; e++) g_gates[(i * 5 + e) * 1024 + o] = v[e] * inv;
}

// ============================================================
// 2) combined conv weights: W[i][t][o][c] = sum_e g[e,o]*expert_e[o,c,t]
// ============================================================
__global__ void build_w_kernel(const float* __restrict__ c5, const float* __restrict__ c3,
                               const float* __restrict__ c1, const float* __restrict__ a3,
                               const float* __restrict__ a5) {
    int idx = blockIdx.x * blockDim.x + threadIdx.x;   // 4M threads: (i,o,c)
    if (idx >= 4 * 1024 * 1024) return;
    int i = idx >> 20;
    int o = (idx >> 10) & 1023;
    int c = idx & 1023;
    int gbase = i * 5120 + o;
    float g0 = g_gates[gbase];
    float g1 = g_gates[gbase + 1024];
    float g2 = g_gates[gbase + 2048];
    float g3 = g_gates[gbase + 3072];
    float g4 = g_gates[gbase + 4096];
    size_t oc = ((size_t)i << 20) + ((size_t)o << 10) + c;
    const float* p5 = c5 + oc * 5;
    const float* p3 = c3 + oc * 3;
    float base = g4 * a5[oc] * 0.2f;                 // avg5 expert: every tap
    float mid  = g3 * a3[oc] * (1.f / 3.f);          // avg3 expert: taps 1..3
    float w0 = g0 * p5[0] + base;
    float w1 = g0 * p5[1] + g1 * p3[0] + mid + base;
    float w2 = g0 * p5[2] + g1 * p3[1] + g2 * c1[oc] + mid + base;
    float w3 = g0 * p5[3] + g1 * p3[2] + mid + base;
    float w4 = g0 * p5[4] + base;
    size_t wb = (((size_t)(i * 5) << 10) + o) * 1024 + c;
    const size_t TS = (size_t)1024 * 1024;
    g_W[wb]          = w0;
    g_W[wb + TS]     = w1;
    g_W[wb + 2 * TS] = w2;
    g_W[wb + 3 * TS] = w3;
    g_W[wb + 4 * TS] = w4;
}

// ============================================================
// 3) conv-as-GEMM body: y[b,l,o] = sum_t sum_c W[wi][t][o][c]*x[b,l+t-2,c]
//    128x128 tile, 256 thr, tf32 mma.sync m16n8k8 inner loop.
//    Per warp: 32 rows x 64 cols (2 m-tiles x 8 n-tiles).
//    Double-buffered smem staging (verified in 4664us baseline);
//    values are rounded to tf32 (rna) at smem-store time.
// ============================================================
__device__ __forceinline__
void conv_body(const float* __restrict__ x, int wi, float* __restrict__ y, int relu,
               float As[2][16][132], float Bs[2][16][132]) {
    int b  = blockIdx.y >> 3;
    int l0 = (blockIdx.y & 7) << 7;
    int o0 = blockIdx.x << 7;
    int tid = threadIdx.x;
    int lane = tid & 31;
    int w    = tid >> 5;           // 0..7
    int g4l  = lane >> 2;          // groupID 0..7
    int t4   = lane & 3;           // threadID-in-group 0..3
    int m0   = (w & 3) << 5;       // 0,32,64,96
    int n0   = (w >> 2) << 6;      // 0,64

    float acc[2][8][4];            // [m-tile][n-tile][frag]
#pragma unroll
    for (int i = 0; i < 2; i++)
#pragma unroll
        for (int j = 0; j < 8; j++)
#pragma unroll
            for (int c = 0; c < 4; c++) acc[i][j][c] = 0.f;

    int ar = tid >> 2;            // 0..63
    int ak = (tid & 3) << 2;      // 0,4,8,12
    const float* xb = x + (((size_t)b) << 20);
    const float* wbase = g_W + (((size_t)(wi * 5)) << 20);

    const int NSTEP = 5 * 64;     // taps x k-chunks
    float4 pa[2], pb[2];

#define CONV_LOAD(s) do { \
    int t_ = (s) >> 6; int k0_ = ((s) & 63) << 4; int dl_ = t_ - 2; \
    const float* wb_ = wbase + ((size_t)t_ << 20); \
    _Pragma("unroll") \
    for (int rr = 0; rr < 2; rr++) { \
        int row = ar + (rr << 6); \
        int lp = l0 + row + dl_; \
        pa[rr] = make_float4(0.f, 0.f, 0.f, 0.f); \
        if ((unsigned)lp < 1024u) \
            pa[rr] = *(const float4*)(xb + (size_t)lp * 1024 + k0_ + ak); \
        pb[rr] = *(const float4*)(wb_ + (size_t)(o0 + row) * 1024 + k0_ + ak); \
    } } while (0)

#define CONV_STORE(bf) do { \
    _Pragma("unroll") \
    for (int rr = 0; rr < 2; rr++) { \
        int row = ar + (rr << 6); \
        As[bf][ak + 0][row] = to_tf32(pa[rr].x); As[bf][ak + 1][row] = to_tf32(pa[rr].y); \
        As[bf][ak + 2][row] = to_tf32(pa[rr].z); As[bf][ak + 3][row] = to_tf32(pa[rr].w); \
        Bs[bf][ak + 0][row] = to_tf32(pb[rr].x); Bs[bf][ak + 1][row] = to_tf32(pb[rr].y); \
        Bs[bf][ak + 2][row] = to_tf32(pb[rr].z); Bs[bf][ak + 3][row] = to_tf32(pb[rr].w); \
    } } while (0)

    CONV_LOAD(0);
    CONV_STORE(0);
    __syncthreads();

    for (int s = 0; s < NSTEP; s++) {
        int buf = s & 1;
        if (s + 1 < NSTEP) CONV_LOAD(s + 1);   // prefetch overlaps compute
#pragma unroll
        for (int ks = 0; ks < 2; ks++) {
            int kk0 = ks << 3;
            uint32_t afr[2][4], bfr[8][2];
#pragma unroll
            for (int i = 0; i < 2; i++) {
                int m = m0 + (i << 4) + g4l;
                afr[i][0] = __float_as_uint(As[buf][kk0 + t4][m]);
                afr[i][1] = __float_as_uint(As[buf][kk0 + t4][m + 8]);
                afr[i][2] = __float_as_uint(As[buf][kk0 + 4 + t4][m]);
                afr[i][3] = __float_as_uint(As[buf][kk0 + 4 + t4][m + 8]);
            }
#pragma unroll
            for (int j = 0; j < 8; j++) {
                int n = n0 + (j << 3) + g4l;
                bfr[j][0] = __float_as_uint(Bs[buf][kk0 + t4][n]);
                bfr[j][1] = __float_as_uint(Bs[buf][kk0 + 4 + t4][n]);
            }
#pragma unroll
            for (int i = 0; i < 2; i++)
#pragma unroll
                for (int j = 0; j < 8; j++)
                    MMA_TF32(acc[i][j], afr[i], bfr[j]);
        }
        if (s + 1 < NSTEP) CONV_STORE(buf ^ 1);
        __syncthreads();
    }
#undef CONV_LOAD
#undef CONV_STORE

    // epilogue: d frag layout rows {g, g+8}, cols {t4*2, t4*2+1}
#pragma unroll
    for (int i = 0; i < 2; i++) {
        int lrow = l0 + m0 + (i << 4) + g4l;
        float* yr0 = y + ((((size_t)b) << 10) + lrow) * 1024 + o0 + n0 + (t4 << 1);
        float* yr1 = yr0 + 8 * 1024;
#pragma unroll
        for (int j = 0; j < 8; j++) {
            float2 v0, v1;
            v0.x = acc[i][j][0]; v0.y = acc[i][j][1];
            v1.x = acc[i][j][2]; v1.y = acc[i][j][3];
            if (relu) {
                v0.x = fmaxf(v0.x, 0.f); v0.y = fmaxf(v0.y, 0.f);
                v1.x = fmaxf(v1.x, 0.f); v1.y = fmaxf(v1.y, 0.f);
            }
            *(float2*)(yr0 + (j << 3)) = v0;
            *(float2*)(yr1 + (j << 3)) = v1;
        }
    }
}

// Q/K/V projections fused into one launch via blockIdx.z
__global__ __launch_bounds__(256)
void conv_qkv_kernel(const float* __restrict__ q, const float* __restrict__ k,
                     const float* __restrict__ v) {
    __shared__ float As[2][16][132];
    __shared__ float Bs[2][16][132];
    int z = blockIdx.z;
    const float* x = (z == 0) ? q : (z == 1) ? k : v;
    conv_body(x, z, g_qkv[z], 1, As, Bs);
}

// final wo projection (reads g_att, no relu)
__global__ __launch_bounds__(256)
void conv_out_kernel(float* __restrict__ out) {
    __shared__ float As[2][16][132];
    __shared__ float Bs[2][16][132];
    conv_body(g_att, 3, out, 0, As, Bs);
}

// ============================================================
// 4) scores = Q K^T / 8 per (b,h): 128x128 tile, K=64  (FFMA2, measured)
// ============================================================
__global__ __launch_bounds__(256)
void scores_kernel() {
    int kc0 = blockIdx.x << 7;
    int q0  = blockIdx.y << 7;
    int bh  = blockIdx.z;
    int b = bh >> 4, h = bh & 15;
    int tid = threadIdx.x;
    int tx = tid & 15, ty = tid >> 4;
    __shared__ float As[16][132];
    __shared__ float Bs[16][132];
    unsigned long long acc2[8][4];
#pragma unroll
    for (int i = 0; i < 8; i++)
#pragma unroll
        for (int j = 0; j < 4; j++) acc2[i][j] = 0ULL;
    int ar = tid >> 2, ak = (tid & 3) << 2;
    const float* Q = g_qkv[0] + (((size_t)b) << 20) + h * 64;
    const float* K = g_qkv[1] + (((size_t)b) << 20) + h * 64;
    for (int k0 = 0; k0 < 64; k0 += 16) {
#pragma unroll
        for (int rr = 0; rr < 2; rr++) {
            int row = ar + (rr << 6);
            float4 av = *(const float4*)(Q + (q0 + row) * 1024 + k0 + ak);
            As[ak + 0][row] = av.x; As[ak + 1][row] = av.y;
            As[ak + 2][row] = av.z; As[ak + 3][row] = av.w;
            float4 bv = *(const float4*)(K + (kc0 + row) * 1024 + k0 + ak);
            Bs[ak + 0][row] = bv.x; Bs[ak + 1][row] = bv.y;
            Bs[ak + 2][row] = bv.z; Bs[ak + 3][row] = bv.w;
        }
        __syncthreads();
#pragma unroll
        for (int kk = 0; kk < 16; kk++) {
            float4 a0 = *(const float4*)&As[kk][ty << 3];
            float4 a1 = *(const float4*)&As[kk][(ty << 3) + 4];
            const unsigned long long* bp =
                (const unsigned long long*)&Bs[kk][tx << 3];
            unsigned long long bb0 = bp[0], bb1 = bp[1];
            unsigned long long bb2 = bp[2], bb3 = bp[3];
            float a[8] = {a0.x, a0.y, a0.z, a0.w, a1.x, a1.y, a1.z, a1.w};
#pragma unroll
            for (int i = 0; i < 8; i++) {
                unsigned long long pav;
                PACK2(pav, a[i]);
                FMA2(acc2[i][0], pav, bb0);
                FMA2(acc2[i][1], pav, bb1);
                FMA2(acc2[i][2], pav, bb2);
                FMA2(acc2[i][3], pav, bb3);
            }
        }
        __syncthreads();
    }
    float* S = g_scores + (((size_t)bh) << 20);
#pragma unroll
    for (int i = 0; i < 8; i++) {
        float* sr = S + (size_t)(q0 + (ty << 3) + i) * 1024 + kc0 + (tx << 3);
#pragma unroll
        for (int j = 0; j < 2; j++) {
            float4 v;
            UNPACK2(v.x, v.y, acc2[i][2 * j]);
            UNPACK2(v.z, v.w, acc2[i][2 * j + 1]);
            v.x *= 0.125f; v.y *= 0.125f; v.z *= 0.125f; v.w *= 0.125f;
            *(float4*)(sr + 4 * j) = v;
        }
    }
}

// ============================================================
// 5) masked softmax over each score row (length 1024)
// ============================================================
__global__ void softmax_kernel(const int* __restrict__ mask) {
    int row = blockIdx.x;                 // bh*1024 + q
    int q = row & 1023;
    int b = row >> 14;                    // row / (16*1024)
    float* s = g_scores + ((size_t)row << 10);
    const int* mrow = mask + ((((size_t)b) << 10) + q) * 1024;
    int tid = threadIdx.x;                // 256 threads, 4 contiguous elems each
    float4 sv = *(const float4*)(s + (tid << 2));
    int4  mv = *(const int4*)(mrow + (tid << 2));
    float v[4];
    v[0] = (mv.x != 0) ? sv.x : -FLT_MAX;
    v[1] = (mv.y != 0) ? sv.y : -FLT_MAX;
    v[2] = (mv.z != 0) ? sv.z : -FLT_MAX;
    v[3] = (mv.w != 0) ? sv.w : -FLT_MAX;
    float mx = fmaxf(fmaxf(v[0], v[1]), fmaxf(v[2], v[3]));
    __shared__ float sred[8];
#pragma unroll
    for (int off = 16; off > 0; off >>= 1)
        mx = fmaxf(mx, __shfl_xor_sync(0xffffffffu, mx, off));
    if ((tid & 31) == 0) sred[tid >> 5] = mx;
    __syncthreads();
    if (tid == 0) {
        float m2 = sred[0];
#pragma unroll
        for (int w = 1; w < 8; w++) m2 = fmaxf(m2, sred[w]);
        sred[0] = m2;
    }
    __syncthreads();
    float rowmax = sred[0];
    __syncthreads();
    float sum = 0.f;
#pragma unroll
    for (int j = 0; j < 4; j++) {
        v[j] = expf(v[j] - rowmax);
        sum += v[j];
    }
#pragma unroll
    for (int off = 16; off > 0; off >>= 1)
        sum += __shfl_xor_sync(0xffffffffu, sum, off);
    if ((tid & 31) == 0) sred[tid >> 5] = sum;
    __syncthreads();
    if (tid == 0) {
        float s2 = 0.f;
#pragma unroll
        for (int w = 0; w < 8; w++) s2 += sred[w];
        sred[0] = s2;
    }
    __syncthreads();
    float inv = 1.f / sred[0];
    float4 ov;
    ov.x = v[0] * inv; ov.y = v[1] * inv;
    ov.z = v[2] * inv; ov.w = v[3] * inv;
    *(float4*)(s + (tid << 2)) = ov;
}

// ============================================================
// 6) out = attn @ V per (b,h): M=1024, N=64, K=1024; 128x64 tile
// ============================================================
__global__ __launch_bounds__(256)
void attnv_kernel() {
    int m0 = blockIdx.x << 7;
    int bh = blockIdx.y;
    int b = bh >> 4, h = bh & 15;
    int tid = threadIdx.x;
    int tx = tid & 15, ty = tid >> 4;
    __shared__ float As[16][132];
    __shared__ float Bs[16][68];
    unsigned long long acc2[8][2];
#pragma unroll
    for (int i = 0; i < 8; i++)
#pragma unroll
        for (int j = 0; j < 2; j++) acc2[i][j] = 0ULL;
    const float* A = g_scores + (((size_t)bh) << 20);
    const float* V = g_qkv[2] + (((size_t)b) << 20) + h * 64;
    int ar = tid >> 2, ak = (tid & 3) << 2;
    int bkk = tid >> 4, bc = (tid & 15) << 2;
    for (int k0 = 0; k0 < 1024; k0 += 16) {
#pragma unroll
        for (int rr = 0; rr < 2; rr++) {
            int row = ar + (rr << 6);
            float4 av = *(const float4*)(A + (size_t)(m0 + row) * 1024 + k0 + ak);
            As[ak + 0][row] = av.x; As[ak + 1][row] = av.y;
            As[ak + 2][row] = av.z; As[ak + 3][row] = av.w;
        }
        {
            float4 bv = *(const float4*)(V + (k0 + bkk) * 1024 + bc);
            *(float4*)&Bs[bkk][bc] = bv;
        }
        __syncthreads();
#pragma unroll
        for (int kk = 0; kk < 16; kk++) {
            float4 a0 = *(const float4*)&As[kk][ty << 3];
            float4 a1 = *(const float4*)&As[kk][(ty << 3) + 4];
            const unsigned long long* bp =
                (const unsigned long long*)&Bs[kk][tx << 2];
            unsigned long long bb0 = bp[0], bb1 = bp[1];
            float a[8] = {a0.x, a0.y, a0.z, a0.w, a1.x, a1.y, a1.z, a1.w};
#pragma unroll
            for (int i = 0; i < 8; i++) {
                unsigned long long pav;
                PACK2(pav, a[i]);
                FMA2(acc2[i][0], pav, bb0);
                FMA2(acc2[i][1], pav, bb1);
            }
        }
        __syncthreads();
    }
#pragma unroll
    for (int i = 0; i < 8; i++) {
        float4 v;
        UNPACK2(v.x, v.y, acc2[i][0]);
        UNPACK2(v.z, v.w, acc2[i][1]);
        float* yr = g_att + ((((size_t)b) << 10) + m0 + (ty << 3) + i) * 1024 + h * 64 + (tx << 2);
        *(float4*)yr = v;
    }
}

// ============================================================
// launch
// ============================================================
extern "C" void kernel_launch(void* const* d_in, const int* in_sizes, int n_in,
                              void* d_out, int out_size) {
    const float* q   = (const float*)d_in[0];
    const float* k   = (const float*)d_in[1];
    const float* v   = (const float*)d_in[2];
    const float* gw  = (const float*)d_in[3];
    const float* gb  = (const float*)d_in[4];
    const float* c5  = (const float*)d_in[5];
    const float* c3  = (const float*)d_in[6];
    const float* c1  = (const float*)d_in[7];
    const float* a3  = (const float*)d_in[8];
    const float* a5  = (const float*)d_in[9];
    const int*   msk = (const int*)d_in[10];
    float* out = (float*)d_out;

    gate_kernel<<<16, 256>>>(gw, gb);
    build_w_kernel<<<16384, 256>>>(c5, c3, c1, a3, a5);

    conv_qkv_kernel<<<dim3(8, 32, 3), 256>>>(q, k, v);

    scores_kernel<<<dim3(8, 8, 64), 256>>>();
    softmax_kernel<<<65536, 256>>>(msk);
    attnv_kernel<<<dim3(8, 64), 256>>>();

    conv_out_kernel<<<dim3(8, 32, 1), 256>>>(out);
}